// round 1
// baseline (speedup 1.0000x reference)
#include <cuda_runtime.h>
#include <math.h>

#define D_DIM 128
#define N_NODES 50000
#define N_EDGES 600000
#define LN_EPS 1e-5f

// Scratch (allocation-free rule: __device__ globals)
__device__ float g_hpre[N_NODES * D_DIM];
__device__ float g_agg [N_NODES * D_DIM];
__device__ float g_t1  [N_NODES * D_DIM];

// ---------------------------------------------------------------------------
// zero agg
// ---------------------------------------------------------------------------
__global__ void zero_kernel(float* __restrict__ p, int n4) {
    int i = blockIdx.x * blockDim.x + threadIdx.x;
    if (i < n4) ((float4*)p)[i] = make_float4(0.f, 0.f, 0.f, 0.f);
}

// ---------------------------------------------------------------------------
// Edge scatter: one warp per edge. agg[dst] += hpre[src]
// ---------------------------------------------------------------------------
__global__ void scatter_kernel(const float* __restrict__ hpre,
                               const int* __restrict__ src,
                               const int* __restrict__ dst,
                               float* __restrict__ agg) {
    int gid  = blockIdx.x * blockDim.x + threadIdx.x;
    int e    = gid >> 5;
    int lane = gid & 31;
    if (e >= N_EDGES) return;
    int s = src[e];
    int d = dst[e];
    float4 v = ((const float4*)(hpre + (size_t)s * D_DIM))[lane];
    float* o = agg + (size_t)d * D_DIM + lane * 4;
    atomicAdd(o + 0, v.x);
    atomicAdd(o + 1, v.y);
    atomicAdd(o + 2, v.z);
    atomicAdd(o + 3, v.w);
}

// ---------------------------------------------------------------------------
// GEMM: out[nrows,128] = act(A[nrows,128] @ W[128,128] + bias)
// MODE 0: plain store     MODE 1: relu store
// MODE 2: v = resid + relu(A@W + bias); out = LayerNorm(v)*gamma + beta
//
// Block: 256 threads, 32 rows x 128 cols tile. Full W in smem (64KB),
// A tile in smem (16KB). Thread computes 4 rows x 4 cols.
// ---------------------------------------------------------------------------
template <int MODE>
__global__ void __launch_bounds__(256, 2)
gemm_kernel(const float* __restrict__ A, const float* __restrict__ W,
            const float* __restrict__ bias, const float* __restrict__ resid,
            const float* __restrict__ gamma, const float* __restrict__ beta,
            float* __restrict__ out, int nrows) {
    extern __shared__ float smem[];
    float* sW = smem;               // 128*128 floats
    float* sA = smem + D_DIM * D_DIM; // 32*128 floats

    const int tid  = threadIdx.x;
    const int base = blockIdx.x * 32;

    // Load W (16384 floats = 4096 float4)
    {
        const float4* W4 = (const float4*)W;
        float4* sW4 = (float4*)sW;
        #pragma unroll
        for (int i = tid; i < (D_DIM * D_DIM) / 4; i += 256) sW4[i] = W4[i];
    }
    // Load A tile (32 rows, zero-pad past nrows)
    {
        const float4* A4 = (const float4*)A;
        float4* sA4 = (float4*)sA;
        #pragma unroll
        for (int i = tid; i < (32 * D_DIM) / 4; i += 256) {
            int r   = i >> 5;          // D/4 = 32 float4 per row
            int row = base + r;
            sA4[i] = (row < nrows) ? A4[(size_t)row * 32 + (i & 31)]
                                   : make_float4(0.f, 0.f, 0.f, 0.f);
        }
    }
    __syncthreads();

    const int cg = tid & 31;   // col group: cols cg*4 .. cg*4+3
    const int rg = tid >> 5;   // row group: rows rg*4 .. rg*4+3 (8 warps)

    float4 acc0 = {0,0,0,0}, acc1 = {0,0,0,0}, acc2 = {0,0,0,0}, acc3 = {0,0,0,0};
    const float* a0 = sA + (rg * 4 + 0) * D_DIM;
    const float* a1 = sA + (rg * 4 + 1) * D_DIM;
    const float* a2 = sA + (rg * 4 + 2) * D_DIM;
    const float* a3 = sA + (rg * 4 + 3) * D_DIM;
    const float4* sW4 = (const float4*)sW;

    #pragma unroll 8
    for (int k = 0; k < D_DIM; k++) {
        float4 w = sW4[k * 32 + cg];
        float x0 = a0[k], x1 = a1[k], x2 = a2[k], x3 = a3[k];
        acc0.x += x0 * w.x; acc0.y += x0 * w.y; acc0.z += x0 * w.z; acc0.w += x0 * w.w;
        acc1.x += x1 * w.x; acc1.y += x1 * w.y; acc1.z += x1 * w.z; acc1.w += x1 * w.w;
        acc2.x += x2 * w.x; acc2.y += x2 * w.y; acc2.z += x2 * w.z; acc2.w += x2 * w.w;
        acc3.x += x3 * w.x; acc3.y += x3 * w.y; acc3.z += x3 * w.z; acc3.w += x3 * w.w;
    }

    // Bias (+relu)
    float4 b = ((const float4*)bias)[cg];
    float4 accs[4] = {acc0, acc1, acc2, acc3};
    #pragma unroll
    for (int i = 0; i < 4; i++) {
        accs[i].x += b.x; accs[i].y += b.y; accs[i].z += b.z; accs[i].w += b.w;
        if (MODE >= 1) {
            accs[i].x = fmaxf(accs[i].x, 0.f);
            accs[i].y = fmaxf(accs[i].y, 0.f);
            accs[i].z = fmaxf(accs[i].z, 0.f);
            accs[i].w = fmaxf(accs[i].w, 0.f);
        }
    }

    if (MODE < 2) {
        float4* out4 = (float4*)out;
        #pragma unroll
        for (int i = 0; i < 4; i++) {
            int row = base + rg * 4 + i;
            if (row < nrows) out4[(size_t)row * 32 + cg] = accs[i];
        }
        return;
    }

    // MODE 2: residual add + LayerNorm, fused.
    // Add residual, stash tile into sA (done reading A), then per-row LN.
    const float4* res4 = (const float4*)resid;
    __syncthreads();   // everyone done reading sA
    float4* sO4 = (float4*)sA;
    #pragma unroll
    for (int i = 0; i < 4; i++) {
        int row = base + rg * 4 + i;
        float4 r = (row < nrows) ? res4[(size_t)row * 32 + cg]
                                 : make_float4(0.f, 0.f, 0.f, 0.f);
        float4 v;
        v.x = accs[i].x + r.x; v.y = accs[i].y + r.y;
        v.z = accs[i].z + r.z; v.w = accs[i].w + r.w;
        sO4[(rg * 4 + i) * 32 + cg] = v;
    }
    __syncthreads();

    // Warp rg handles rows rg*4..rg*4+3; lane = cg handles 4 cols.
    float4 gm = ((const float4*)gamma)[cg];
    float4 bt = ((const float4*)beta)[cg];
    float4* out4 = (float4*)out;
    #pragma unroll
    for (int i = 0; i < 4; i++) {
        int lr  = rg * 4 + i;
        int row = base + lr;
        float4 v = sO4[lr * 32 + cg];
        float s  = v.x + v.y + v.z + v.w;
        float s2 = v.x * v.x + v.y * v.y + v.z * v.z + v.w * v.w;
        #pragma unroll
        for (int off = 16; off > 0; off >>= 1) {
            s  += __shfl_xor_sync(0xFFFFFFFFu, s,  off);
            s2 += __shfl_xor_sync(0xFFFFFFFFu, s2, off);
        }
        float mean = s * (1.0f / D_DIM);
        float var  = s2 * (1.0f / D_DIM) - mean * mean;
        float rstd = rsqrtf(var + LN_EPS);
        float4 o;
        o.x = (v.x - mean) * rstd * gm.x + bt.x;
        o.y = (v.y - mean) * rstd * gm.y + bt.y;
        o.z = (v.z - mean) * rstd * gm.z + bt.z;
        o.w = (v.w - mean) * rstd * gm.w + bt.w;
        if (row < nrows) out4[(size_t)row * 32 + cg] = o;
    }
}

// ---------------------------------------------------------------------------
extern "C" void kernel_launch(void* const* d_in, const int* in_sizes, int n_in,
                              void* d_out, int out_size) {
    const float* h     = (const float*)d_in[0];
    const int*   src   = (const int*)  d_in[1];
    const int*   dst   = (const int*)  d_in[2];
    const float* W_pre = (const float*)d_in[3];
    const float* b_pre = (const float*)d_in[4];
    const float* W1    = (const float*)d_in[5];
    const float* b1    = (const float*)d_in[6];
    const float* W2    = (const float*)d_in[7];
    const float* b2    = (const float*)d_in[8];
    const float* gamma = (const float*)d_in[9];
    const float* beta  = (const float*)d_in[10];
    float* out = (float*)d_out;

    float *hpre, *agg, *t1;
    cudaGetSymbolAddress((void**)&hpre, g_hpre);
    cudaGetSymbolAddress((void**)&agg,  g_agg);
    cudaGetSymbolAddress((void**)&t1,   g_t1);

    const int smem_bytes = (D_DIM * D_DIM + 32 * D_DIM) * sizeof(float); // 80KB
    cudaFuncSetAttribute(gemm_kernel<0>, cudaFuncAttributeMaxDynamicSharedMemorySize, smem_bytes);
    cudaFuncSetAttribute(gemm_kernel<1>, cudaFuncAttributeMaxDynamicSharedMemorySize, smem_bytes);
    cudaFuncSetAttribute(gemm_kernel<2>, cudaFuncAttributeMaxDynamicSharedMemorySize, smem_bytes);

    const int gemm_blocks = (N_NODES + 31) / 32;  // 1563

    // 1. zero agg
    {
        int n4 = N_NODES * D_DIM / 4;
        zero_kernel<<<(n4 + 255) / 256, 256>>>(agg, n4);
    }
    // 2. hpre = h @ W_pre + b_pre
    gemm_kernel<0><<<gemm_blocks, 256, smem_bytes>>>(h, W_pre, b_pre,
                                                     nullptr, nullptr, nullptr,
                                                     hpre, N_NODES);
    // 3. agg[dst] += hpre[src]  (warp per edge)
    {
        long long threads = (long long)N_EDGES * 32;
        int blocks = (int)((threads + 255) / 256);
        scatter_kernel<<<blocks, 256>>>(hpre, src, dst, agg);
    }
    // 4. t1 = relu(agg @ W1 + b1)
    gemm_kernel<1><<<gemm_blocks, 256, smem_bytes>>>(agg, W1, b1,
                                                     nullptr, nullptr, nullptr,
                                                     t1, N_NODES);
    // 5. out = LayerNorm(hpre + relu(t1 @ W2 + b2)) * gamma + beta
    gemm_kernel<2><<<gemm_blocks, 256, smem_bytes>>>(t1, W2, b2,
                                                     hpre, gamma, beta,
                                                     out, N_NODES);
    (void)in_sizes; (void)n_in; (void)out_size;
}

// round 2
// speedup vs baseline: 1.5304x; 1.5304x over previous
#include <cuda_runtime.h>
#include <math.h>

#define D_DIM 128
#define N_NODES 50000
#define N_EDGES 600000
#define LN_EPS 1e-5f

// Scratch (allocation-free rule: __device__ globals)
__device__ float g_hpre[N_NODES * D_DIM];
__device__ float g_agg [N_NODES * D_DIM];
__device__ float g_t1  [N_NODES * D_DIM];

// ---------------------------------------------------------------------------
// zero agg
// ---------------------------------------------------------------------------
__global__ void zero_kernel(float* __restrict__ p, int n4) {
    int i = blockIdx.x * blockDim.x + threadIdx.x;
    if (i < n4) ((float4*)p)[i] = make_float4(0.f, 0.f, 0.f, 0.f);
}

// ---------------------------------------------------------------------------
// Edge scatter: one warp per edge. agg[dst] += hpre[src]
// One red.global.add.v4.f32 per lane (16B vector reduction, sm_90+).
// ---------------------------------------------------------------------------
__global__ void scatter_kernel(const float* __restrict__ hpre,
                               const int* __restrict__ src,
                               const int* __restrict__ dst,
                               float* __restrict__ agg) {
    int gid  = blockIdx.x * blockDim.x + threadIdx.x;
    int e    = gid >> 5;
    int lane = gid & 31;
    if (e >= N_EDGES) return;
    int s = src[e];
    int d = dst[e];
    float4 v = ((const float4*)(hpre + (size_t)s * D_DIM))[lane];
    float* o = agg + (size_t)d * D_DIM + lane * 4;
    asm volatile("red.global.add.v4.f32 [%0], {%1, %2, %3, %4};"
                 :: "l"(o), "f"(v.x), "f"(v.y), "f"(v.z), "f"(v.w)
                 : "memory");
}

// ---------------------------------------------------------------------------
// GEMM: out[nrows,128] = act(A[nrows,128] @ W[128,128] + bias)
// MODE 0: plain store     MODE 1: relu store
// MODE 2: v = resid + relu(A@W + bias); out = LayerNorm(v)*gamma + beta
//
// Block: 256 threads, 64 rows x 128 cols tile. Full W in smem (64KB),
// A tile in smem (32KB). Thread computes 8 rows x 4 cols; k stepped by 4
// with A row-chunks loaded as broadcast float4 -> FMA-bound smem mix.
// ---------------------------------------------------------------------------
#define TILE_ROWS 64

template <int MODE>
__global__ void __launch_bounds__(256, 2)
gemm_kernel(const float* __restrict__ A, const float* __restrict__ W,
            const float* __restrict__ bias, const float* __restrict__ resid,
            const float* __restrict__ gamma, const float* __restrict__ beta,
            float* __restrict__ out, int nrows) {
    extern __shared__ float smem[];
    float* sW = smem;                    // 128*128 floats = 64KB
    float* sA = smem + D_DIM * D_DIM;    // 64*128 floats  = 32KB

    const int tid  = threadIdx.x;
    const int base = blockIdx.x * TILE_ROWS;

    // Load W (16384 floats = 4096 float4)
    {
        const float4* W4 = (const float4*)W;
        float4* sW4 = (float4*)sW;
        #pragma unroll
        for (int i = tid; i < (D_DIM * D_DIM) / 4; i += 256) sW4[i] = W4[i];
    }
    // Load A tile (64 rows x 32 float4, zero-pad past nrows)
    {
        const float4* A4 = (const float4*)A;
        float4* sA4 = (float4*)sA;
        #pragma unroll
        for (int i = tid; i < (TILE_ROWS * D_DIM) / 4; i += 256) {
            int r   = i >> 5;
            int row = base + r;
            sA4[i] = (row < nrows) ? A4[(size_t)row * 32 + (i & 31)]
                                   : make_float4(0.f, 0.f, 0.f, 0.f);
        }
    }
    __syncthreads();

    const int cg = tid & 31;   // col group: cols cg*4 .. cg*4+3 (lane id)
    const int rg = tid >> 5;   // warp id: rows rg*8 .. rg*8+7

    float4 acc[8];
    #pragma unroll
    for (int i = 0; i < 8; i++) acc[i] = make_float4(0.f, 0.f, 0.f, 0.f);

    const float4* sW4 = (const float4*)sW;
    const float4* sA4 = (const float4*)sA;
    const int rowbase = rg * 8;

    #pragma unroll 4
    for (int k0 = 0; k0 < D_DIM; k0 += 4) {
        // 4 consecutive k-slices of W for this lane's 4 columns
        float4 w0 = sW4[(k0 + 0) * 32 + cg];
        float4 w1 = sW4[(k0 + 1) * 32 + cg];
        float4 w2 = sW4[(k0 + 2) * 32 + cg];
        float4 w3 = sW4[(k0 + 3) * 32 + cg];
        #pragma unroll
        for (int r = 0; r < 8; r++) {
            // broadcast read: whole warp reads same address
            float4 a = sA4[(rowbase + r) * 32 + (k0 >> 2)];
            acc[r].x += a.x * w0.x; acc[r].y += a.x * w0.y;
            acc[r].z += a.x * w0.z; acc[r].w += a.x * w0.w;
            acc[r].x += a.y * w1.x; acc[r].y += a.y * w1.y;
            acc[r].z += a.y * w1.z; acc[r].w += a.y * w1.w;
            acc[r].x += a.z * w2.x; acc[r].y += a.z * w2.y;
            acc[r].z += a.z * w2.z; acc[r].w += a.z * w2.w;
            acc[r].x += a.w * w3.x; acc[r].y += a.w * w3.y;
            acc[r].z += a.w * w3.z; acc[r].w += a.w * w3.w;
        }
    }

    // Bias (+relu)
    float4 b = ((const float4*)bias)[cg];
    #pragma unroll
    for (int i = 0; i < 8; i++) {
        acc[i].x += b.x; acc[i].y += b.y; acc[i].z += b.z; acc[i].w += b.w;
        if (MODE >= 1) {
            acc[i].x = fmaxf(acc[i].x, 0.f);
            acc[i].y = fmaxf(acc[i].y, 0.f);
            acc[i].z = fmaxf(acc[i].z, 0.f);
            acc[i].w = fmaxf(acc[i].w, 0.f);
        }
    }

    float4* out4 = (float4*)out;

    if (MODE < 2) {
        #pragma unroll
        for (int i = 0; i < 8; i++) {
            int row = base + rowbase + i;
            if (row < nrows) out4[(size_t)row * 32 + cg] = acc[i];
        }
        return;
    }

    // MODE 2: residual add + LayerNorm — fully in registers + warp shuffles.
    // Each lane owns 4 columns of its 8 rows; the warp covers all 128 cols.
    const float4* res4 = (const float4*)resid;
    float4 gm = ((const float4*)gamma)[cg];
    float4 bt = ((const float4*)beta)[cg];
    #pragma unroll
    for (int i = 0; i < 8; i++) {
        int row = base + rowbase + i;
        float4 r = (row < nrows) ? res4[(size_t)row * 32 + cg]
                                 : make_float4(0.f, 0.f, 0.f, 0.f);
        float4 v;
        v.x = acc[i].x + r.x; v.y = acc[i].y + r.y;
        v.z = acc[i].z + r.z; v.w = acc[i].w + r.w;
        float s  = v.x + v.y + v.z + v.w;
        float s2 = v.x * v.x + v.y * v.y + v.z * v.z + v.w * v.w;
        #pragma unroll
        for (int off = 16; off > 0; off >>= 1) {
            s  += __shfl_xor_sync(0xFFFFFFFFu, s,  off);
            s2 += __shfl_xor_sync(0xFFFFFFFFu, s2, off);
        }
        float mean = s * (1.0f / D_DIM);
        float var  = s2 * (1.0f / D_DIM) - mean * mean;
        float rstd = rsqrtf(var + LN_EPS);
        float4 o;
        o.x = (v.x - mean) * rstd * gm.x + bt.x;
        o.y = (v.y - mean) * rstd * gm.y + bt.y;
        o.z = (v.z - mean) * rstd * gm.z + bt.z;
        o.w = (v.w - mean) * rstd * gm.w + bt.w;
        if (row < nrows) out4[(size_t)row * 32 + cg] = o;
    }
}

// ---------------------------------------------------------------------------
extern "C" void kernel_launch(void* const* d_in, const int* in_sizes, int n_in,
                              void* d_out, int out_size) {
    const float* h     = (const float*)d_in[0];
    const int*   src   = (const int*)  d_in[1];
    const int*   dst   = (const int*)  d_in[2];
    const float* W_pre = (const float*)d_in[3];
    const float* b_pre = (const float*)d_in[4];
    const float* W1    = (const float*)d_in[5];
    const float* b1    = (const float*)d_in[6];
    const float* W2    = (const float*)d_in[7];
    const float* b2    = (const float*)d_in[8];
    const float* gamma = (const float*)d_in[9];
    const float* beta  = (const float*)d_in[10];
    float* out = (float*)d_out;

    float *hpre, *agg, *t1;
    cudaGetSymbolAddress((void**)&hpre, g_hpre);
    cudaGetSymbolAddress((void**)&agg,  g_agg);
    cudaGetSymbolAddress((void**)&t1,   g_t1);

    const int smem_bytes = (D_DIM * D_DIM + TILE_ROWS * D_DIM) * sizeof(float); // 96KB
    cudaFuncSetAttribute(gemm_kernel<0>, cudaFuncAttributeMaxDynamicSharedMemorySize, smem_bytes);
    cudaFuncSetAttribute(gemm_kernel<1>, cudaFuncAttributeMaxDynamicSharedMemorySize, smem_bytes);
    cudaFuncSetAttribute(gemm_kernel<2>, cudaFuncAttributeMaxDynamicSharedMemorySize, smem_bytes);

    const int gemm_blocks = (N_NODES + TILE_ROWS - 1) / TILE_ROWS;  // 782

    // 1. zero agg
    {
        int n4 = N_NODES * D_DIM / 4;
        zero_kernel<<<(n4 + 255) / 256, 256>>>(agg, n4);
    }
    // 2. hpre = h @ W_pre + b_pre
    gemm_kernel<0><<<gemm_blocks, 256, smem_bytes>>>(h, W_pre, b_pre,
                                                     nullptr, nullptr, nullptr,
                                                     hpre, N_NODES);
    // 3. agg[dst] += hpre[src]  (warp per edge, vectorized red)
    {
        long long threads = (long long)N_EDGES * 32;
        int blocks = (int)((threads + 255) / 256);
        scatter_kernel<<<blocks, 256>>>(hpre, src, dst, agg);
    }
    // 4. t1 = relu(agg @ W1 + b1)
    gemm_kernel<1><<<gemm_blocks, 256, smem_bytes>>>(agg, W1, b1,
                                                     nullptr, nullptr, nullptr,
                                                     t1, N_NODES);
    // 5. out = LayerNorm(hpre + relu(t1 @ W2 + b2)) * gamma + beta
    gemm_kernel<2><<<gemm_blocks, 256, smem_bytes>>>(t1, W2, b2,
                                                     hpre, gamma, beta,
                                                     out, N_NODES);
    (void)in_sizes; (void)n_in; (void)out_size;
}